// round 4
// baseline (speedup 1.0000x reference)
#include <cuda_runtime.h>

#define NB     4096
#define MAXKV  64
#define CTA    256          // 8 warps/CTA, 1 warp per logical block
#define GRID   (NB / 8)     // 512 CTAs -> 4096 warps, fully chip-resident

// Per-block scratch + barrier state. All state is either fully overwritten
// each launch or reset by the last CTA -> graph-replay safe.
__device__ float g_psum[NB];   // sum over block of p*keep
__device__ float g_kcnt[NB];   // sum over block of keep
__device__ float g_bce[NB];    // sum over block of bce*sup
__device__ float g_sup[NB];    // sum over block of sup
__device__ float g_gl[NB];     // blk_loss * valid
__device__ float g_val[NB];    // valid flag
__device__ int   g_bar;        // grid barrier arrivals
__device__ int   g_flag;       // grid barrier release flag
__device__ int   g_done;       // completion counter (last-CTA-done)

__device__ __forceinline__ float warp_sum(float v) {
#pragma unroll
    for (int o = 16; o > 0; o >>= 1) v += __shfl_down_sync(0xffffffffu, v, o);
    return v;
}

__global__ void __launch_bounds__(CTA) fused(const float4* __restrict__ x4,
                                             const float4* __restrict__ t4,
                                             const uint4*  __restrict__ s4,
                                             const uint4*  __restrict__ i4,
                                             const int*    __restrict__ kvi,
                                             const int*    __restrict__ kvn,
                                             float* __restrict__ out) {
    const int tid  = threadIdx.x;
    const int lane = tid & 31;
    const int gw   = blockIdx.x * 8 + (tid >> 5);   // logical block b

    // ---- Early loads: neighbor metadata (1 MB, DRAM) hides under phase A ----
    const int nb = kvn[gw];
    const int j0 = kvi[gw * MAXKV + lane];
    const int j1 = kvi[gw * MAXKV + 32 + lane];

    // ---- Phase A: per-node math, 7 per-block scalars ----
    const int vidx = gw * 32 + lane;
    const float4 xv = x4[vidx];
    const float4 tv = t4[vidx];
    const uint4  sv = s4[vidx];
    const uint4  iv = i4[vidx];

    float bce_s = 0.f, sup_s = 0.f, pk_s = 0.f, k_s = 0.f;
    float p1 = 0.f, p2 = 0.f, q = 0.f;   // Σp·unc, Σp²·unc, Σunc
    {
        const float xs[4] = {xv.x, xv.y, xv.z, xv.w};
        const float ts[4] = {tv.x, tv.y, tv.z, tv.w};
        const unsigned int ss[4] = {sv.x, sv.y, sv.z, sv.w};
        const unsigned int is[4] = {iv.x, iv.y, iv.z, iv.w};
#pragma unroll
        for (int k = 0; k < 4; k++) {
            const float x = xs[k];
            const float e = __expf(-fabsf(x));          // one exp for both
            const float inv = 1.0f / (1.0f + e);
            const float p  = (x >= 0.0f) ? inv : e * inv;
            const float sp = fmaxf(x, 0.0f) + __logf(1.0f + e);
            const bool s    = ss[k] != 0u;
            const bool keep = is[k] == 0u;
            if (s)         { bce_s += sp - ts[k] * x; sup_s += 1.0f; }
            if (keep)      { pk_s  += p;              k_s   += 1.0f; }
            if (keep && !s){ p1 += p; p2 += p * p;    q     += 1.0f; }
        }
    }
    bce_s = warp_sum(bce_s); sup_s = warp_sum(sup_s);
    pk_s  = warp_sum(pk_s);  k_s   = warp_sum(k_s);
    p1    = warp_sum(p1);    p2    = warp_sum(p2);    q = warp_sum(q);
    if (lane == 0) {
        g_psum[gw] = pk_s;
        g_kcnt[gw] = k_s;
    }

    // ---- Grid barrier (all 512 CTAs resident -> spin is safe) ----
    __syncthreads();
    if (tid == 0) {
        __threadfence();
        if (atomicAdd(&g_bar, 1) == GRID - 1) {
            atomicExch(&g_flag, 1);
        } else {
            volatile int* vf = &g_flag;
            while (*vf == 0) __nanosleep(64);
        }
    }
    __syncthreads();
    __threadfence();   // acquire: make other CTAs' g_psum/g_kcnt visible

    // ---- Phase B: scalar-only neighbor gather -> n_mean; closed-form blk loss ----
    float ns = 0.0f, nc = 0.0f;
    if (lane < nb)      { ns += g_psum[j0]; nc += g_kcnt[j0]; }
    if (lane + 32 < nb) { ns += g_psum[j1]; nc += g_kcnt[j1]; }
    ns = warp_sum(ns); nc = warp_sum(nc);
    if (lane == 0) {
        const float m = ns / fmaxf(nc, 1.0f);
        // Σ_unc (p-m)^2 = p2 - 2m*p1 + q*m^2
        const float sq = p2 - 2.0f * m * p1 + q * m * m;
        const bool valid = (q > 0.0f) && (nc > 0.0f);
        g_gl[gw]  = valid ? (sq / fmaxf(q, 1.0f)) : 0.0f;
        g_val[gw] = valid ? 1.0f : 0.0f;
        g_bce[gw] = bce_s;
        g_sup[gw] = sup_s;
    }

    // ---- Last-CTA-done: final reduction + state reset ----
    __syncthreads();
    __shared__ int s_last;
    if (tid == 0) {
        __threadfence();
        s_last = (atomicAdd(&g_done, 1) == GRID - 1) ? 1 : 0;
    }
    __syncthreads();
    if (!s_last) return;

    __threadfence();   // acquire all CTAs' phase-B writes
    float a = 0.f, b = 0.f, c = 0.f, d = 0.f;
    for (int i = tid; i < NB; i += CTA) {
        a += g_bce[i];
        b += g_sup[i];
        c += g_gl[i];
        d += g_val[i];
    }
    __shared__ float sh[4][8];
    a = warp_sum(a); b = warp_sum(b); c = warp_sum(c); d = warp_sum(d);
    const int w = tid >> 5;
    if (lane == 0) { sh[0][w] = a; sh[1][w] = b; sh[2][w] = c; sh[3][w] = d; }
    __syncthreads();
    if (tid == 0) {
        float A = 0.f, B = 0.f, C = 0.f, D = 0.f;
#pragma unroll
        for (int i = 0; i < 8; i++) { A += sh[0][i]; B += sh[1][i]; C += sh[2][i]; D += sh[3][i]; }
        const float loss_sup   = (B > 0.0f) ? (A / fmaxf(B, 1.0f)) : 0.0f;
        const float loss_graph = C / fmaxf(D, 1.0f);
        out[0] = loss_sup + 0.3f * loss_graph;
        // reset barrier state for the next graph replay
        g_bar  = 0;
        g_flag = 0;
        g_done = 0;
    }
}

extern "C" void kernel_launch(void* const* d_in, const int* in_sizes, int n_in,
                              void* d_out, int out_size) {
    const float4* x4 = (const float4*)d_in[0];  // logits   [524288] f32
    const float4* t4 = (const float4*)d_in[1];  // targets  [524288] f32
    const uint4*  s4 = (const uint4*)d_in[2];   // sup_mask  (4-byte bool)
    const uint4*  i4 = (const uint4*)d_in[3];   // ignore_mask
    const int*   kvi = (const int*)d_in[4];     // kv_indices [4096*64]
    const int*   kvn = (const int*)d_in[5];     // kv_num_blocks [4096]
    (void)in_sizes; (void)n_in; (void)out_size;

    fused<<<GRID, CTA>>>(x4, t4, s4, i4, kvi, kvn, (float*)d_out);
}

// round 5
// speedup vs baseline: 1.1193x; 1.1193x over previous
#include <cuda_runtime.h>

#define NB     4096
#define MAXKV  64
#define CTA    256

// Per-block scratch. g_done is reset by its last user each launch -> replay safe.
__device__ float g_psum[NB];   // Σ p·keep
__device__ float g_kcnt[NB];   // Σ keep
__device__ float g_bce[NB];    // Σ bce·sup
__device__ float g_sup[NB];    // Σ sup
__device__ float g_p1[NB];     // Σ p·unc
__device__ float g_p2[NB];     // Σ p²·unc
__device__ float g_q[NB];      // Σ unc
__device__ float g_gl[NB];     // blk_loss·valid
__device__ float g_val[NB];    // valid flag
__device__ int   g_done;       // last-CTA-done counter (zero-init, reset after use)

__device__ __forceinline__ float warp_sum(float v) {
#pragma unroll
    for (int o = 16; o > 0; o >>= 1) v += __shfl_down_sync(0xffffffffu, v, o);
    return v;
}

// ---------------- Kernel A: per-node math, 7 per-block scalars, 2 blocks/warp ----------------
__global__ void __launch_bounds__(CTA) kernA(const float4* __restrict__ x4,
                                             const float4* __restrict__ t4,
                                             const uint4*  __restrict__ s4,
                                             const uint4*  __restrict__ i4) {
    const int lane = threadIdx.x & 31;
    const int gw   = blockIdx.x * 8 + (threadIdx.x >> 5);  // 0..2047; handles blocks 2gw, 2gw+1
    const int base = gw * 64 + lane;                       // float4 index

    // Front-batched loads: 8 independent LDG.128 (MLP_p1 = 8)
    const float4 xv0 = x4[base];        const float4 xv1 = x4[base + 32];
    const float4 tv0 = t4[base];        const float4 tv1 = t4[base + 32];
    const uint4  sv0 = s4[base];        const uint4  sv1 = s4[base + 32];
    const uint4  iv0 = i4[base];        const uint4  iv1 = i4[base + 32];

#pragma unroll
    for (int half = 0; half < 2; half++) {
        const float4 xv = half ? xv1 : xv0;
        const float4 tv = half ? tv1 : tv0;
        const uint4  sv = half ? sv1 : sv0;
        const uint4  iv = half ? iv1 : iv0;

        float bce_s = 0.f, sup_s = 0.f, pk_s = 0.f, k_s = 0.f;
        float p1 = 0.f, p2 = 0.f, q = 0.f;
        const float xs[4] = {xv.x, xv.y, xv.z, xv.w};
        const float ts[4] = {tv.x, tv.y, tv.z, tv.w};
        const unsigned int ss[4] = {sv.x, sv.y, sv.z, sv.w};
        const unsigned int is[4] = {iv.x, iv.y, iv.z, iv.w};
#pragma unroll
        for (int k = 0; k < 4; k++) {
            const float x = xs[k];
            const float e   = __expf(-fabsf(x));           // one exp for softplus+sigmoid
            const float inv = 1.0f / (1.0f + e);
            const float p   = (x >= 0.0f) ? inv : e * inv;
            const float sp  = fmaxf(x, 0.0f) + __logf(1.0f + e);
            const bool s    = ss[k] != 0u;
            const bool keep = is[k] == 0u;
            if (s)          { bce_s += sp - ts[k] * x; sup_s += 1.0f; }
            if (keep)       { pk_s  += p;              k_s   += 1.0f; }
            if (keep && !s) { p1 += p; p2 += p * p;    q     += 1.0f; }
        }
        bce_s = warp_sum(bce_s); sup_s = warp_sum(sup_s);
        pk_s  = warp_sum(pk_s);  k_s   = warp_sum(k_s);
        p1    = warp_sum(p1);    p2    = warp_sum(p2);    q = warp_sum(q);
        if (lane == 0) {
            const int b = 2 * gw + half;
            g_bce[b]  = bce_s;  g_sup[b]  = sup_s;
            g_psum[b] = pk_s;   g_kcnt[b] = k_s;
            g_p1[b]   = p1;     g_p2[b]   = p2;    g_q[b] = q;
        }
    }
}

// ---------------- Kernel B: scalar neighbor gather + closed-form loss + last-CTA final reduce ----------------
#define GRIDB (NB / 8)   // 512 CTAs, warp per block
__global__ void __launch_bounds__(CTA) kernB(const int* __restrict__ kvi,
                                             const int* __restrict__ kvn,
                                             float* __restrict__ out) {
    const int tid  = threadIdx.x;
    const int lane = tid & 31;
    const int b    = blockIdx.x * 8 + (tid >> 5);

    const int nb = kvn[b];
    const int j0 = kvi[b * MAXKV + lane];
    const int j1 = kvi[b * MAXKV + 32 + lane];

    float ns = 0.0f, nc = 0.0f;
    if (lane < nb)      { ns += g_psum[j0]; nc += g_kcnt[j0]; }
    if (lane + 32 < nb) { ns += g_psum[j1]; nc += g_kcnt[j1]; }
    ns = warp_sum(ns); nc = warp_sum(nc);
    if (lane == 0) {
        const float m  = ns / fmaxf(nc, 1.0f);
        const float p1 = g_p1[b], p2 = g_p2[b], q = g_q[b];
        const float sq = p2 - 2.0f * m * p1 + q * m * m;   // Σ_unc (p-m)²
        const bool valid = (q > 0.0f) && (nc > 0.0f);
        g_gl[b]  = valid ? (sq / fmaxf(q, 1.0f)) : 0.0f;
        g_val[b] = valid ? 1.0f : 0.0f;
    }

    // ---- last-CTA-done final reduction ----
    __syncthreads();
    __shared__ int s_last;
    if (tid == 0) {
        __threadfence();
        s_last = (atomicAdd(&g_done, 1) == GRIDB - 1) ? 1 : 0;
    }
    __syncthreads();
    if (!s_last) return;

    __threadfence();   // acquire all CTAs' g_gl/g_val writes
    float a = 0.f, bb = 0.f, c = 0.f, d = 0.f;
    for (int i = tid; i < NB; i += CTA) {
        a  += g_bce[i];
        bb += g_sup[i];
        c  += g_gl[i];
        d  += g_val[i];
    }
    __shared__ float sh[4][8];
    a = warp_sum(a); bb = warp_sum(bb); c = warp_sum(c); d = warp_sum(d);
    const int w = tid >> 5;
    if (lane == 0) { sh[0][w] = a; sh[1][w] = bb; sh[2][w] = c; sh[3][w] = d; }
    __syncthreads();
    if (tid == 0) {
        float A = 0.f, B = 0.f, C = 0.f, D = 0.f;
#pragma unroll
        for (int i = 0; i < 8; i++) { A += sh[0][i]; B += sh[1][i]; C += sh[2][i]; D += sh[3][i]; }
        const float loss_sup   = (B > 0.0f) ? (A / fmaxf(B, 1.0f)) : 0.0f;
        const float loss_graph = C / fmaxf(D, 1.0f);
        out[0] = loss_sup + 0.3f * loss_graph;
        g_done = 0;   // reset for next graph replay
    }
}

extern "C" void kernel_launch(void* const* d_in, const int* in_sizes, int n_in,
                              void* d_out, int out_size) {
    const float4* x4 = (const float4*)d_in[0];  // logits   [524288] f32
    const float4* t4 = (const float4*)d_in[1];  // targets  [524288] f32
    const uint4*  s4 = (const uint4*)d_in[2];   // sup_mask  (4-byte bool)
    const uint4*  i4 = (const uint4*)d_in[3];   // ignore_mask
    const int*   kvi = (const int*)d_in[4];     // kv_indices [4096*64]
    const int*   kvn = (const int*)d_in[5];     // kv_num_blocks [4096]
    (void)in_sizes; (void)n_in; (void)out_size;

    kernA<<<256, CTA>>>(x4, t4, s4, i4);
    kernB<<<GRIDB, CTA>>>(kvi, kvn, (float*)d_out);
}

// round 6
// speedup vs baseline: 1.1964x; 1.0688x over previous
#include <cuda_runtime.h>

#define NB     4096
#define MAXKV  64
#define CTA    256
#define GRIDAB (NB / 8)   // 512 CTAs, warp per logical block

// Packed per-block scratch. Fully rewritten each launch (g_done reset by last user).
__device__ float2 g_pk[NB];    // (Σ p·keep, Σ keep)        <- gathered by neighbors
__device__ float2 g_bs[NB];    // (Σ bce·sup, Σ sup)
__device__ float4 g_own[NB];   // (Σ p·unc, Σ p²·unc, Σ unc, 0)
__device__ float2 g_gv[NB];    // (blk_loss·valid, valid)
__device__ int    g_pref[NB];  // dummy sink for kvi L2-prefetch
__device__ int    g_done;      // last-CTA-done counter

__device__ __forceinline__ float warp_sum(float v) {
#pragma unroll
    for (int o = 16; o > 0; o >>= 1) v += __shfl_down_sync(0xffffffffu, v, o);
    return v;
}

// ---------------- Kernel A: per-node math, packed per-block scalars, kvi L2 prefetch ----------------
__global__ void __launch_bounds__(CTA) kernA(const float4* __restrict__ x4,
                                             const float4* __restrict__ t4,
                                             const uint4*  __restrict__ s4,
                                             const uint4*  __restrict__ i4,
                                             const uint2*  __restrict__ kvi2,
                                             const int*    __restrict__ kvn) {
    const int lane = threadIdx.x & 31;
    const int b    = blockIdx.x * 8 + (threadIdx.x >> 5);   // logical block
    const int vidx = b * 32 + lane;

    // Front-batched independent loads (MLP ~6): 4 data vecs + kvi row prefetch + kvn
    const float4 xv = x4[vidx];
    const float4 tv = t4[vidx];
    const uint4  sv = s4[vidx];
    const uint4  iv = i4[vidx];
    const uint2  pf = kvi2[vidx];          // this block's kvi row: 32 lanes x 2 ints = 64
    const int    pn = (lane == 0) ? kvn[b] : 0;

    float bce_s = 0.f, sup_s = 0.f, pk_s = 0.f, k_s = 0.f;
    float p1 = 0.f, p2 = 0.f, q = 0.f;
    {
        const float xs[4] = {xv.x, xv.y, xv.z, xv.w};
        const float ts[4] = {tv.x, tv.y, tv.z, tv.w};
        const unsigned int ss[4] = {sv.x, sv.y, sv.z, sv.w};
        const unsigned int is[4] = {iv.x, iv.y, iv.z, iv.w};
#pragma unroll
        for (int k = 0; k < 4; k++) {
            const float x = xs[k];
            const float e   = __expf(-fabsf(x));            // one exp for softplus+sigmoid
            const float inv = 1.0f / (1.0f + e);
            const float p   = (x >= 0.0f) ? inv : e * inv;
            const float sp  = fmaxf(x, 0.0f) + __logf(1.0f + e);
            const bool s    = ss[k] != 0u;
            const bool keep = is[k] == 0u;
            if (s)          { bce_s += sp - ts[k] * x; sup_s += 1.0f; }
            if (keep)       { pk_s  += p;              k_s   += 1.0f; }
            if (keep && !s) { p1 += p; p2 += p * p;    q     += 1.0f; }
        }
    }
    bce_s = warp_sum(bce_s); sup_s = warp_sum(sup_s);
    pk_s  = warp_sum(pk_s);  k_s   = warp_sum(k_s);
    p1    = warp_sum(p1);    p2    = warp_sum(p2);    q = warp_sum(q);
    if (lane == 0) {
        g_pk[b]  = make_float2(pk_s, k_s);
        g_bs[b]  = make_float2(bce_s, sup_s);
        g_own[b] = make_float4(p1, p2, q, 0.0f);
        g_pref[b] = (int)(pf.x ^ pf.y) + pn;   // keep prefetch loads alive
    }
}

// ---------------- Kernel B: scalar neighbor gather + closed-form loss + last-CTA final reduce ----------------
__global__ void __launch_bounds__(CTA) kernB(const uint2* __restrict__ kvi2,
                                             const int*   __restrict__ kvn,
                                             float* __restrict__ out) {
    const int tid  = threadIdx.x;
    const int lane = tid & 31;
    const int b    = blockIdx.x * 8 + (tid >> 5);

    // kvi row (L2-hot from kernA prefetch): lane covers neighbors 2*lane, 2*lane+1
    const uint2 jj = kvi2[b * 32 + lane];
    const int   nb = kvn[b];

    float ns = 0.0f, nc = 0.0f;
    if (2 * lane < nb)     { const float2 v = g_pk[jj.x]; ns += v.x; nc += v.y; }
    if (2 * lane + 1 < nb) { const float2 v = g_pk[jj.y]; ns += v.x; nc += v.y; }
    ns = warp_sum(ns); nc = warp_sum(nc);
    if (lane == 0) {
        const float  m  = ns / fmaxf(nc, 1.0f);
        const float4 ow = g_own[b];                       // (p1, p2, q, 0)
        const float  sq = ow.y - 2.0f * m * ow.x + ow.z * m * m;  // Σ_unc (p-m)²
        const bool valid = (ow.z > 0.0f) && (nc > 0.0f);
        g_gv[b] = make_float2(valid ? (sq / fmaxf(ow.z, 1.0f)) : 0.0f,
                              valid ? 1.0f : 0.0f);
    }

    // ---- last-CTA-done final reduction ----
    __syncthreads();
    __shared__ int s_last;
    if (tid == 0) {
        __threadfence();
        s_last = (atomicAdd(&g_done, 1) == GRIDAB - 1) ? 1 : 0;
    }
    __syncthreads();
    if (!s_last) return;

    __threadfence();   // acquire all CTAs' g_gv writes
    float a = 0.f, bb = 0.f, c = 0.f, d = 0.f;
    for (int i = tid; i < NB; i += CTA) {
        const float2 bs = g_bs[i];
        const float2 gv = g_gv[i];
        a  += bs.x;
        bb += bs.y;
        c  += gv.x;
        d  += gv.y;
    }
    __shared__ float sh[4][8];
    a = warp_sum(a); bb = warp_sum(bb); c = warp_sum(c); d = warp_sum(d);
    const int w = tid >> 5;
    if (lane == 0) { sh[0][w] = a; sh[1][w] = bb; sh[2][w] = c; sh[3][w] = d; }
    __syncthreads();
    if (tid == 0) {
        float A = 0.f, B = 0.f, C = 0.f, D = 0.f;
#pragma unroll
        for (int i = 0; i < 8; i++) { A += sh[0][i]; B += sh[1][i]; C += sh[2][i]; D += sh[3][i]; }
        const float loss_sup   = (B > 0.0f) ? (A / fmaxf(B, 1.0f)) : 0.0f;
        const float loss_graph = C / fmaxf(D, 1.0f);
        out[0] = loss_sup + 0.3f * loss_graph;
        g_done = 0;   // reset for next graph replay
    }
}

extern "C" void kernel_launch(void* const* d_in, const int* in_sizes, int n_in,
                              void* d_out, int out_size) {
    const float4* x4   = (const float4*)d_in[0];  // logits   [524288] f32
    const float4* t4   = (const float4*)d_in[1];  // targets  [524288] f32
    const uint4*  s4   = (const uint4*)d_in[2];   // sup_mask  (4-byte bool)
    const uint4*  i4   = (const uint4*)d_in[3];   // ignore_mask
    const uint2*  kvi2 = (const uint2*)d_in[4];   // kv_indices [4096*64] viewed as uint2
    const int*    kvn  = (const int*)d_in[5];     // kv_num_blocks [4096]
    (void)in_sizes; (void)n_in; (void)out_size;

    kernA<<<GRIDAB, CTA>>>(x4, t4, s4, i4, kvi2, kvn);
    kernB<<<GRIDAB, CTA>>>(kvi2, kvn, (float*)d_out);
}

// round 7
// speedup vs baseline: 1.2737x; 1.0647x over previous
#include <cuda_runtime.h>

#define NB     4096
#define MAXKV  64
#define CTA    128              // 4 warps/CTA
#define GRIDAB (NB / 4)         // 1024 CTAs -> 4096 warps, warp per logical block

// Packed per-block scratch. Fully rewritten each launch (g_done reset by last user).
__device__ float2 g_pk[NB];    // (Σ p·keep, Σ keep)   <- gathered by neighbors
__device__ float2 g_bs[NB];    // (Σ bce·sup, Σ sup)
__device__ float4 g_own[NB];   // (Σ p·unc, Σ p²·unc, Σ unc, 0)
__device__ float2 g_gv[NB];    // (blk_loss·valid, valid)
__device__ int    g_done;      // last-CTA-done counter (zero-init, reset after use)

__device__ __forceinline__ float warp_sum(float v) {
#pragma unroll
    for (int o = 16; o > 0; o >>= 1) v += __shfl_down_sync(0xffffffffu, v, o);
    return v;
}

// ---------------- Kernel A: per-node math -> 7 packed per-block scalars ----------------
__global__ void __launch_bounds__(CTA) kernA(const float4* __restrict__ x4,
                                             const float4* __restrict__ t4,
                                             const uint4*  __restrict__ s4,
                                             const uint4*  __restrict__ i4) {
    const int lane = threadIdx.x & 31;
    const int b    = blockIdx.x * 4 + (threadIdx.x >> 5);   // logical block
    const int vidx = b * 32 + lane;

    // Front-batched independent LDG.128 x4
    const float4 xv = x4[vidx];
    const float4 tv = t4[vidx];
    const uint4  sv = s4[vidx];
    const uint4  iv = i4[vidx];

    float bce_s = 0.f, sup_s = 0.f, pk_s = 0.f, k_s = 0.f;
    float p1 = 0.f, p2 = 0.f, q = 0.f;
    {
        const float xs[4] = {xv.x, xv.y, xv.z, xv.w};
        const float ts[4] = {tv.x, tv.y, tv.z, tv.w};
        const unsigned int ss[4] = {sv.x, sv.y, sv.z, sv.w};
        const unsigned int is[4] = {iv.x, iv.y, iv.z, iv.w};
#pragma unroll
        for (int k = 0; k < 4; k++) {
            const float x = xs[k];
            const float e   = __expf(-fabsf(x));            // one exp for softplus+sigmoid
            const float inv = 1.0f / (1.0f + e);
            const float p   = (x >= 0.0f) ? inv : e * inv;
            const float sp  = fmaxf(x, 0.0f) + __logf(1.0f + e);
            const bool s    = ss[k] != 0u;
            const bool keep = is[k] == 0u;
            if (s)          { bce_s += sp - ts[k] * x; sup_s += 1.0f; }
            if (keep)       { pk_s  += p;              k_s   += 1.0f; }
            if (keep && !s) { p1 += p; p2 += p * p;    q     += 1.0f; }
        }
    }
    bce_s = warp_sum(bce_s); sup_s = warp_sum(sup_s);
    pk_s  = warp_sum(pk_s);  k_s   = warp_sum(k_s);
    p1    = warp_sum(p1);    p2    = warp_sum(p2);    q = warp_sum(q);
    if (lane == 0) {
        g_pk[b]  = make_float2(pk_s, k_s);
        g_bs[b]  = make_float2(bce_s, sup_s);
        g_own[b] = make_float4(p1, p2, q, 0.0f);
    }
}

// ---------------- Kernel B: scalar neighbor gather + closed-form loss + last-CTA reduce ----------------
__global__ void __launch_bounds__(CTA) kernB(const uint2* __restrict__ kvi2,
                                             const int*   __restrict__ kvn,
                                             float* __restrict__ out) {
    const int tid  = threadIdx.x;
    const int lane = tid & 31;
    const int b    = blockIdx.x * 4 + (tid >> 5);

    // lane covers neighbors 2*lane, 2*lane+1 (one LDG.64 for the pair of indices)
    const uint2 jj = kvi2[b * 32 + lane];
    const int   nb = kvn[b];

    float ns = 0.0f, nc = 0.0f;
    if (2 * lane < nb)     { const float2 v = g_pk[jj.x]; ns += v.x; nc += v.y; }
    if (2 * lane + 1 < nb) { const float2 v = g_pk[jj.y]; ns += v.x; nc += v.y; }
    ns = warp_sum(ns); nc = warp_sum(nc);
    if (lane == 0) {
        const float  m  = ns / fmaxf(nc, 1.0f);
        const float4 ow = g_own[b];                              // (p1, p2, q, 0)
        const float  sq = ow.y - 2.0f * m * ow.x + ow.z * m * m; // Σ_unc (p-m)²
        const bool valid = (ow.z > 0.0f) && (nc > 0.0f);
        g_gv[b] = make_float2(valid ? (sq / fmaxf(ow.z, 1.0f)) : 0.0f,
                              valid ? 1.0f : 0.0f);
    }

    // ---- last-CTA-done final reduction ----
    __syncthreads();
    __shared__ int s_last;
    if (tid == 0) {
        __threadfence();                    // release this CTA's g_gv writes
        s_last = (atomicAdd(&g_done, 1) == GRIDAB - 1) ? 1 : 0;
    }
    __syncthreads();
    if (!s_last) return;

    __threadfence();                        // acquire all CTAs' g_gv writes
    float a = 0.f, bb = 0.f, c = 0.f, d = 0.f;
    for (int i = tid; i < NB; i += CTA) {
        const float2 bs = g_bs[i];
        const float2 gv = g_gv[i];
        a  += bs.x;
        bb += bs.y;
        c  += gv.x;
        d  += gv.y;
    }
    __shared__ float sh[4][4];
    a = warp_sum(a); bb = warp_sum(bb); c = warp_sum(c); d = warp_sum(d);
    const int w = tid >> 5;
    if (lane == 0) { sh[0][w] = a; sh[1][w] = bb; sh[2][w] = c; sh[3][w] = d; }
    __syncthreads();
    if (tid == 0) {
        float A = 0.f, B = 0.f, C = 0.f, D = 0.f;
#pragma unroll
        for (int i = 0; i < 4; i++) { A += sh[0][i]; B += sh[1][i]; C += sh[2][i]; D += sh[3][i]; }
        const float loss_sup   = (B > 0.0f) ? (A / fmaxf(B, 1.0f)) : 0.0f;
        const float loss_graph = C / fmaxf(D, 1.0f);
        out[0] = loss_sup + 0.3f * loss_graph;
        g_done = 0;   // reset for next graph replay
    }
}

extern "C" void kernel_launch(void* const* d_in, const int* in_sizes, int n_in,
                              void* d_out, int out_size) {
    const float4* x4   = (const float4*)d_in[0];  // logits   [524288] f32
    const float4* t4   = (const float4*)d_in[1];  // targets  [524288] f32
    const uint4*  s4   = (const uint4*)d_in[2];   // sup_mask  (4-byte bool)
    const uint4*  i4   = (const uint4*)d_in[3];   // ignore_mask
    const uint2*  kvi2 = (const uint2*)d_in[4];   // kv_indices [4096*64] as uint2
    const int*    kvn  = (const int*)d_in[5];     // kv_num_blocks [4096]
    (void)in_sizes; (void)n_in; (void)out_size;

    kernA<<<GRIDAB, CTA>>>(x4, t4, s4, i4);
    kernB<<<GRIDAB, CTA>>>(kvi2, kvn, (float*)d_out);
}